// round 2
// baseline (speedup 1.0000x reference)
#include <cuda_runtime.h>
#include <cstdint>
#include <cstddef>

#define BB 64
#define TT 512
#define AA 128
#define HH 512
#define G4 2048  // 4*H

// ---------------- scratch (static device allocations; no cudaMalloc) ----------------
__device__ float g_pre[(size_t)TT * BB * G4];   // 256MB: pre-gates  [t][b][4H]
__device__ float g_hall[(size_t)TT * BB * HH];  // 64MB : h history  [t][b][H]
__device__ float g_h[2][BB * HH];               // double-buffered recurrent h
__device__ float g_c[BB * HH];                  // cell state
__device__ float g_wp[(size_t)BB * AA * HH];    // 16MB : W'[b] = w_out + w_out@M[b]

// ---------------- init: h0, c0 -> state ----------------
__global__ void k_init(const float* __restrict__ h0, const float* __restrict__ c0) {
    int i = blockIdx.x * blockDim.x + threadIdx.x;
    if (i < BB * HH) { g_h[0][i] = h0[i]; g_c[i] = c0[i]; }
}

// ---------------- kernel 1: pre[t][b][row] = bias[row] + x[b][t] . w_ih[row] ----------------
// GEMM: M=64 (b, fixed t per block), N=2048 (gate rows), K=128. NT layout (both K-major).
__global__ __launch_bounds__(256) void k_pregates(const float* __restrict__ x,
                                                  const float* __restrict__ w_ih,
                                                  const float* __restrict__ b_ih,
                                                  const float* __restrict__ b_hh) {
    __shared__ float As[64][68];
    __shared__ float Bs[64][68];
    const int t  = blockIdx.y;
    const int n0 = blockIdx.x * 64;
    const int tid = threadIdx.x;
    const int tm = tid >> 4;   // 0..15 -> m = tm*4+i  (b)
    const int tn = tid & 15;   // 0..15 -> n = tn*4+j  (row)
    float acc[4][4] = {};

    for (int k0 = 0; k0 < AA; k0 += 64) {
#pragma unroll
        for (int i = 0; i < 4; i++) {
            int id = tid + i * 256;
            int r = id >> 4, c4 = (id & 15) << 2;
            *(float4*)&As[r][c4] = *(const float4*)&x[((size_t)r * TT + t) * AA + k0 + c4];
            *(float4*)&Bs[r][c4] = *(const float4*)&w_ih[(size_t)(n0 + r) * AA + k0 + c4];
        }
        __syncthreads();
#pragma unroll
        for (int k = 0; k < 64; k += 4) {
            float4 a[4], b[4];
#pragma unroll
            for (int i = 0; i < 4; i++) a[i] = *(const float4*)&As[tm * 4 + i][k];
#pragma unroll
            for (int j = 0; j < 4; j++) b[j] = *(const float4*)&Bs[tn * 4 + j][k];
#pragma unroll
            for (int i = 0; i < 4; i++)
#pragma unroll
                for (int j = 0; j < 4; j++)
                    acc[i][j] += a[i].x * b[j].x + a[i].y * b[j].y + a[i].z * b[j].z + a[i].w * b[j].w;
        }
        __syncthreads();
    }
    float4 bi = *(const float4*)&b_ih[n0 + tn * 4];
    float4 bh = *(const float4*)&b_hh[n0 + tn * 4];
    float4 bias = make_float4(bi.x + bh.x, bi.y + bh.y, bi.z + bh.z, bi.w + bh.w);
#pragma unroll
    for (int i = 0; i < 4; i++) {
        int m = tm * 4 + i;
        float4 v = make_float4(acc[i][0] + bias.x, acc[i][1] + bias.y,
                               acc[i][2] + bias.z, acc[i][3] + bias.w);
        *(float4*)&g_pre[((size_t)t * BB + m) * G4 + n0 + tn * 4] = v;
    }
}

// ---------------- kernel 2: W'[b] = w_out + w_out @ M[b] ----------------
// GEMM per b: M=128 (a), N=512 (i), K=512 (j). NN layout.
__global__ __launch_bounds__(256) void k_wprime(const float* __restrict__ w_out,
                                                const float* __restrict__ Mm) {
    __shared__ float As[64][68];
    __shared__ float Bs[64][68];
    const int b  = blockIdx.z;
    const int m0 = blockIdx.y * 64;  // a
    const int n0 = blockIdx.x * 64;  // i
    const int tid = threadIdx.x;
    const int tm = tid >> 4, tn = tid & 15;
    float acc[4][4] = {};

    for (int k0 = 0; k0 < HH; k0 += 64) {
#pragma unroll
        for (int i = 0; i < 4; i++) {
            int id = tid + i * 256;
            int r = id >> 4, c4 = (id & 15) << 2;
            *(float4*)&As[r][c4] = *(const float4*)&w_out[(size_t)(m0 + r) * HH + k0 + c4];
            *(float4*)&Bs[r][c4] = *(const float4*)&Mm[((size_t)b * HH + k0 + r) * HH + n0 + c4];
        }
        __syncthreads();
#pragma unroll
        for (int k = 0; k < 64; k += 4) {
            float4 a[4];
#pragma unroll
            for (int i = 0; i < 4; i++) a[i] = *(const float4*)&As[tm * 4 + i][k];
#pragma unroll
            for (int kk = 0; kk < 4; kk++) {
                float4 bv = *(const float4*)&Bs[k + kk][tn * 4];
#pragma unroll
                for (int i = 0; i < 4; i++) {
                    float av = (kk == 0) ? a[i].x : (kk == 1) ? a[i].y : (kk == 2) ? a[i].z : a[i].w;
                    acc[i][0] += av * bv.x; acc[i][1] += av * bv.y;
                    acc[i][2] += av * bv.z; acc[i][3] += av * bv.w;
                }
            }
        }
        __syncthreads();
    }
#pragma unroll
    for (int i = 0; i < 4; i++) {
        int m = m0 + tm * 4 + i;
        float4 w0 = *(const float4*)&w_out[(size_t)m * HH + n0 + tn * 4];
        float4 v = make_float4(acc[i][0] + w0.x, acc[i][1] + w0.y,
                               acc[i][2] + w0.z, acc[i][3] + w0.w);
        *(float4*)&g_wp[((size_t)b * AA + m) * HH + n0 + tn * 4] = v;
    }
}

// ---------------- kernel 3: one recurrent step (fused gates GEMM + LSTM pointwise) ----
// Block owns j0 = blockIdx.x*4 -> 4 hidden units x 4 gates = 16 w_hh rows, all 64 batches.
__global__ __launch_bounds__(256) void k_step(const float* __restrict__ w_hh, int t) {
    __shared__ float hs[64][68];
    __shared__ float ws[16][68];
    __shared__ float gbuf[64][17];

    const float* __restrict__ pre_t  = g_pre + (size_t)t * BB * G4;
    const float* __restrict__ h_prev = g_h[t & 1];
    float* __restrict__ h_next       = g_h[(t + 1) & 1];
    float* __restrict__ h_all_t      = g_hall + (size_t)t * BB * HH;

    const int j0  = blockIdx.x * 4;
    const int tid = threadIdx.x;
    const int tm  = tid & 31;   // b in {tm, tm+32}
    const int tn  = tid >> 5;   // rows n in {2tn, 2tn+1}
    float acc[2][2] = {};

    for (int k0 = 0; k0 < HH; k0 += 64) {
#pragma unroll
        for (int i = 0; i < 4; i++) {
            int id = tid + i * 256;
            int r = id >> 4, c4 = (id & 15) << 2;
            *(float4*)&hs[r][c4] = *(const float4*)&h_prev[r * HH + k0 + c4];
        }
        {   // 16 rows x 64 k = 256 float4: one per thread
            int r = tid >> 4;               // n = 0..15
            int c4 = (tid & 15) << 2;
            int g = r >> 2, jj = r & 3;
            int row = g * HH + j0 + jj;
            *(float4*)&ws[r][c4] = *(const float4*)&w_hh[(size_t)row * HH + k0 + c4];
        }
        __syncthreads();
#pragma unroll
        for (int k = 0; k < 64; k += 4) {
            float4 h0 = *(const float4*)&hs[tm][k];
            float4 h1 = *(const float4*)&hs[tm + 32][k];
            float4 w0 = *(const float4*)&ws[tn * 2][k];
            float4 w1 = *(const float4*)&ws[tn * 2 + 1][k];
            acc[0][0] += h0.x * w0.x + h0.y * w0.y + h0.z * w0.z + h0.w * w0.w;
            acc[0][1] += h0.x * w1.x + h0.y * w1.y + h0.z * w1.z + h0.w * w1.w;
            acc[1][0] += h1.x * w0.x + h1.y * w0.y + h1.z * w0.z + h1.w * w0.w;
            acc[1][1] += h1.x * w1.x + h1.y * w1.y + h1.z * w1.z + h1.w * w1.w;
        }
        __syncthreads();
    }

    // add precomputed input projection + bias, stash gates
#pragma unroll
    for (int i = 0; i < 2; i++)
#pragma unroll
        for (int j = 0; j < 2; j++) {
            int b = tm + 32 * i;
            int n = tn * 2 + j;
            int g = n >> 2, jj = n & 3;
            int row = g * HH + j0 + jj;
            gbuf[b][n] = acc[i][j] + __ldg(&pre_t[(size_t)b * G4 + row]);
        }
    __syncthreads();

    // LSTM pointwise: 256 threads = 64 b x 4 j
    {
        int b  = tid & 63;
        int jj = tid >> 6;
        float xi = gbuf[b][jj];        // gate i (rows 0..511)
        float xf = gbuf[b][4 + jj];    // gate f
        float xg = gbuf[b][8 + jj];    // gate g
        float xo = gbuf[b][12 + jj];   // gate o
        float si = 1.0f / (1.0f + __expf(-xi));
        float sf = 1.0f / (1.0f + __expf(-xf));
        float so = 1.0f / (1.0f + __expf(-xo));
        float tg = tanhf(xg);
        int idx = b * HH + j0 + jj;
        float cn = sf * g_c[idx] + si * tg;
        g_c[idx] = cn;
        float hn = so * tanhf(cn);
        h_next[idx]  = hn;
        h_all_t[idx] = hn;
    }
}

// ---------------- kernel 4: out[b][t][a] = h_all[t][b] . W'[b][a] + b_out[a] ----------
// GEMM per b: M=512 (t), N=128 (a), K=512 (i). NT layout.
__global__ __launch_bounds__(256) void k_out(const float* __restrict__ b_out,
                                             float* __restrict__ out) {
    __shared__ float As[64][68];
    __shared__ float Bs[64][68];
    const int b  = blockIdx.z;
    const int m0 = blockIdx.y * 64;  // t
    const int n0 = blockIdx.x * 64;  // a
    const int tid = threadIdx.x;
    const int tm = tid >> 4, tn = tid & 15;
    float acc[4][4] = {};

    for (int k0 = 0; k0 < HH; k0 += 64) {
#pragma unroll
        for (int i = 0; i < 4; i++) {
            int id = tid + i * 256;
            int r = id >> 4, c4 = (id & 15) << 2;
            *(float4*)&As[r][c4] = *(const float4*)&g_hall[((size_t)(m0 + r) * BB + b) * HH + k0 + c4];
            *(float4*)&Bs[r][c4] = *(const float4*)&g_wp[((size_t)b * AA + n0 + r) * HH + k0 + c4];
        }
        __syncthreads();
#pragma unroll
        for (int k = 0; k < 64; k += 4) {
            float4 a[4], bv[4];
#pragma unroll
            for (int i = 0; i < 4; i++) a[i] = *(const float4*)&As[tm * 4 + i][k];
#pragma unroll
            for (int j = 0; j < 4; j++) bv[j] = *(const float4*)&Bs[tn * 4 + j][k];
#pragma unroll
            for (int i = 0; i < 4; i++)
#pragma unroll
                for (int j = 0; j < 4; j++)
                    acc[i][j] += a[i].x * bv[j].x + a[i].y * bv[j].y + a[i].z * bv[j].z + a[i].w * bv[j].w;
        }
        __syncthreads();
    }
    float4 bo = *(const float4*)&b_out[n0 + tn * 4];
#pragma unroll
    for (int i = 0; i < 4; i++) {
        int m = m0 + tm * 4 + i;
        float4 v = make_float4(acc[i][0] + bo.x, acc[i][1] + bo.y,
                               acc[i][2] + bo.z, acc[i][3] + bo.w);
        *(float4*)&out[((size_t)b * TT + m) * AA + n0 + tn * 4] = v;
    }
}

// ---------------- launch ----------------
extern "C" void kernel_launch(void* const* d_in, const int* in_sizes, int n_in,
                              void* d_out, int out_size) {
    const float* x     = (const float*)d_in[0];
    const float* w_ih  = (const float*)d_in[1];
    const float* w_hh  = (const float*)d_in[2];
    const float* b_ih  = (const float*)d_in[3];
    const float* b_hh  = (const float*)d_in[4];
    const float* Mm    = (const float*)d_in[5];
    const float* w_out = (const float*)d_in[6];
    const float* b_out = (const float*)d_in[7];
    const float* h0    = (const float*)d_in[8];
    const float* c0    = (const float*)d_in[9];
    float* out = (float*)d_out;

    k_init<<<(BB * HH + 255) / 256, 256>>>(h0, c0);
    k_pregates<<<dim3(G4 / 64, TT), 256>>>(x, w_ih, b_ih, b_hh);
    k_wprime<<<dim3(HH / 64, AA / 64, BB), 256>>>(w_out, Mm);

    for (int t = 0; t < TT; ++t)
        k_step<<<HH / 4, 256>>>(w_hh, t);

    k_out<<<dim3(AA / 64, TT / 64, BB), 256>>>(b_out, out);
}